// round 1
// baseline (speedup 1.0000x reference)
#include <cuda_runtime.h>

// StructuredDeepLinear: 1000 Monarch layers, DIM=1024 (M=32 blocks of 32x32), BATCH=512.
//
// Sample-parallel persistent kernel: each CTA owns 4 samples, keeps activations
// resident in SMEM for all 1000 layers, streams weights from GMEM/L2 to registers.
// The Monarch block-transpose is folded into the SMEM addressing convention:
//   a phase reads  in[p][r]  at  src[r*33 + p]   (lane-consecutive -> conflict-free)
//   a phase writes out[p][q] at  dst[p*33 + q]   (banks (p+q)%32   -> conflict-free)
// which makes the transposed output of phase k exactly the expected input layout
// of phase k+1 (verified against the einsum/transpose algebra of the reference).

#define BATCHPER 4     // samples per CTA
#define NCTA     128   // 128 * 4 = 512 = BATCH
#define NTHREADS 256
#define DEPTH    1000
#define PAD      33
#define ROWS     (32 * PAD)   // 1056 floats per sample per buffer

// Computes out[p][q] = sum_r in[p][r] * W[p*1024 + q*32 + r]  for q in [kg*4, kg*4+4)
// for each of the BATCHPER samples. p = lane id (0..31), kg = tid>>5 (0..7).
__device__ __forceinline__ void phase(const float* __restrict__ src,   // [BATCHPER][ROWS]
                                      float*       __restrict__ dst,   // [BATCHPER][ROWS]
                                      const float* __restrict__ W,
                                      int p, int kg)
{
    float acc[BATCHPER][4];
#pragma unroll
    for (int b = 0; b < BATCHPER; ++b)
#pragma unroll
        for (int j = 0; j < 4; ++j) acc[b][j] = 0.0f;

    // Weight rows for this thread: W[p*1024 + (kg*4+j)*32 + r], r contiguous.
    const float* wrow = W + p * 1024 + kg * 128;

#pragma unroll
    for (int mt = 0; mt < 8; ++mt) {
        float4 wv[4];
#pragma unroll
        for (int j = 0; j < 4; ++j)
            wv[j] = *reinterpret_cast<const float4*>(wrow + j * 32 + mt * 4);

#pragma unroll
        for (int b = 0; b < BATCHPER; ++b) {
            const float* s = src + b * ROWS;
            float h0 = s[(4 * mt + 0) * PAD + p];
            float h1 = s[(4 * mt + 1) * PAD + p];
            float h2 = s[(4 * mt + 2) * PAD + p];
            float h3 = s[(4 * mt + 3) * PAD + p];
#pragma unroll
            for (int j = 0; j < 4; ++j) {
                acc[b][j] = fmaf(h0, wv[j].x, acc[b][j]);
                acc[b][j] = fmaf(h1, wv[j].y, acc[b][j]);
                acc[b][j] = fmaf(h2, wv[j].z, acc[b][j]);
                acc[b][j] = fmaf(h3, wv[j].w, acc[b][j]);
            }
        }
    }

    // Transposed-layout store: out[p][q] -> dst[p*33 + q]; conflict-free.
#pragma unroll
    for (int b = 0; b < BATCHPER; ++b) {
        float* d = dst + b * ROWS;
#pragma unroll
        for (int j = 0; j < 4; ++j)
            d[p * PAD + kg * 4 + j] = acc[b][j];
    }
}

__global__ void __launch_bounds__(NTHREADS, 1)
monarch_kernel(const float* __restrict__ x,
               const float* __restrict__ L,
               const float* __restrict__ R,
               float* __restrict__ out)
{
    __shared__ float bufA[BATCHPER * ROWS];
    __shared__ float bufB[BATCHPER * ROWS];

    const int tid = threadIdx.x;
    const int p   = tid & 31;
    const int kg  = tid >> 5;
    const int b0  = blockIdx.x * BATCHPER;

    // Load x: logical H[n][m] (d = n*32+m) stored at [m*33 + n].
    for (int i = tid; i < BATCHPER * 1024; i += NTHREADS) {
        int b = i >> 10, d = i & 1023;
        int n = d >> 5,  m = d & 31;
        bufA[b * ROWS + m * PAD + n] = x[(size_t)(b0 + b) * 1024 + d];
    }
    __syncthreads();

    const float* Wl = L;
    const float* Wr = R;
    for (int layer = 0; layer < DEPTH; ++layer) {
        phase(bufA, bufB, Wl, p, kg);
        __syncthreads();
        phase(bufB, bufA, Wr, p, kg);
        __syncthreads();
        Wl += 32768;
        Wr += 32768;
    }

    // Store: final value at dim d = n*32+m lives at [m*33 + n] (same convention).
    for (int i = tid; i < BATCHPER * 1024; i += NTHREADS) {
        int b = i >> 10, d = i & 1023;
        int n = d >> 5,  m = d & 31;
        out[(size_t)(b0 + b) * 1024 + d] = bufA[b * ROWS + m * PAD + n];
    }
}

extern "C" void kernel_launch(void* const* d_in, const int* in_sizes, int n_in,
                              void* d_out, int out_size)
{
    const float* x = (const float*)d_in[0];
    const float* L = (const float*)d_in[1];
    const float* R = (const float*)d_in[2];
    float* out = (float*)d_out;
    monarch_kernel<<<NCTA, NTHREADS>>>(x, L, R, out);
}